// round 1
// baseline (speedup 1.0000x reference)
#include <cuda_runtime.h>
#include <math.h>

#define S   2048
#define D   2048
#define DFF 8192
#define H   16
#define DH  128

// ---------------------------------------------------------------------------
// Scratch (device globals; no allocation allowed)
// ---------------------------------------------------------------------------
__device__ float g_normed[(size_t)S * D];
__device__ float g_q[(size_t)S * D];
__device__ float g_k[(size_t)S * D];
__device__ float g_v[(size_t)S * D];
__device__ float g_vT[(size_t)S * D];          // [D][S]: vT[h*DH+d][s]
__device__ float g_attn[(size_t)S * D];
__device__ float g_x1[(size_t)S * D];
__device__ float g_scores[(size_t)H * S * S];  // 268 MB, reused as P in-place
__device__ float g_gate[(size_t)S * DFF];
__device__ float g_up[(size_t)S * DFF];

// ---------------------------------------------------------------------------
// RMSNorm: one block per row
// ---------------------------------------------------------------------------
__global__ __launch_bounds__(256) void rmsnorm_kernel(
    const float* __restrict__ x, const float* __restrict__ w,
    float* __restrict__ out)
{
    __shared__ float red[256];
    const int r = blockIdx.x;
    const int tid = threadIdx.x;
    const float* xr = x + (size_t)r * D;

    float ss = 0.0f;
    for (int j = tid; j < D; j += 256) {
        float v = xr[j];
        ss += v * v;
    }
    red[tid] = ss;
    __syncthreads();
    for (int s = 128; s > 0; s >>= 1) {
        if (tid < s) red[tid] += red[tid + s];
        __syncthreads();
    }
    const float sc = rsqrtf(red[0] / (float)D + 1e-6f);
    float* orow = out + (size_t)r * D;
    for (int j = tid; j < D; j += 256)
        orow[j] = xr[j] * sc * w[j];
}

// ---------------------------------------------------------------------------
// Generic batched NT GEMM: C[z][m][n] = s * sum_k A[z][m][k] * B[z][n][k]
//                                       (+ R[m][n]) (+ alpha[z]*Xadd[z][m][n])
// Tiles: 128x128x8, 256 threads, 8x8 micro-tile per thread.
// grid = (N/128, M/128, Z); M,N multiples of 128; K multiple of 8.
// causal_mode: 0 = none
//              1 = skip blocks with bn > bm (scores GEMM, BM==BN)
//              2 = limit K loop to (bm+1)*128 (PV GEMM; P==0 beyond diagonal)
// ---------------------------------------------------------------------------
__global__ __launch_bounds__(256) void gemm_nt(
    const float* __restrict__ A, int lda, long long zA,
    const float* __restrict__ B, int ldb, long long zB,
    float* __restrict__ C, int ldc, long long zC,
    int K,
    const float* __restrict__ scale_ptr, float scale_const,
    const float* __restrict__ R, int ldr,
    const float* __restrict__ Xadd, int ldx, long long zX,
    const float* __restrict__ alpha,
    int causal_mode)
{
    const int bm = blockIdx.y;
    const int bn = blockIdx.x;
    const int bz = blockIdx.z;

    if (causal_mode == 1 && bn > bm) return;
    const int kEnd = (causal_mode == 2) ? min(K, (bm + 1) * 128) : K;

    __shared__ __align__(16) float As[8][128];
    __shared__ __align__(16) float Bs[8][128];

    const int tid = threadIdx.x;
    const int lr  = tid >> 1;          // 0..127 : tile row loaded by this thread
    const int lq  = (tid & 1) * 4;     // 0 or 4 : k-quad
    const int tx4 = (tid & 15) * 4;
    const int ty4 = (tid >> 4) * 4;

    const float* Ab = A + (long long)bz * zA + (size_t)(bm * 128) * lda;
    const float* Bb = B + (long long)bz * zB + (size_t)(bn * 128) * ldb;

    float acc[8][8];
#pragma unroll
    for (int i = 0; i < 8; i++)
#pragma unroll
        for (int j = 0; j < 8; j++)
            acc[i][j] = 0.0f;

    for (int k0 = 0; k0 < kEnd; k0 += 8) {
        float4 av = *(const float4*)(Ab + (size_t)lr * lda + k0 + lq);
        float4 bv = *(const float4*)(Bb + (size_t)lr * ldb + k0 + lq);
        As[lq + 0][lr] = av.x; As[lq + 1][lr] = av.y;
        As[lq + 2][lr] = av.z; As[lq + 3][lr] = av.w;
        Bs[lq + 0][lr] = bv.x; Bs[lq + 1][lr] = bv.y;
        Bs[lq + 2][lr] = bv.z; Bs[lq + 3][lr] = bv.w;
        __syncthreads();

#pragma unroll
        for (int kk = 0; kk < 8; kk++) {
            float4 a0 = *(const float4*)&As[kk][ty4];
            float4 a1 = *(const float4*)&As[kk][ty4 + 64];
            float4 b0 = *(const float4*)&Bs[kk][tx4];
            float4 b1 = *(const float4*)&Bs[kk][tx4 + 64];
            float a[8] = {a0.x, a0.y, a0.z, a0.w, a1.x, a1.y, a1.z, a1.w};
            float b[8] = {b0.x, b0.y, b0.z, b0.w, b1.x, b1.y, b1.z, b1.w};
#pragma unroll
            for (int i = 0; i < 8; i++)
#pragma unroll
                for (int j = 0; j < 8; j++)
                    acc[i][j] += a[i] * b[j];
        }
        __syncthreads();
    }

    float s = scale_const;
    if (scale_ptr) s *= *scale_ptr;
    const float al = alpha ? alpha[bz] : 0.0f;

#pragma unroll
    for (int i = 0; i < 8; i++) {
        const int ri = (i < 4) ? (ty4 + i) : (64 + ty4 + i - 4);
        const size_t row = (size_t)(bm * 128 + ri);
#pragma unroll
        for (int jb = 0; jb < 2; jb++) {
            const int cj = (jb == 0) ? tx4 : (64 + tx4);
            const size_t col = (size_t)(bn * 128 + cj);
            float vals[4];
#pragma unroll
            for (int c = 0; c < 4; c++) {
                float v = acc[i][jb * 4 + c] * s;
                if (R)    v += R[row * ldr + col + c];
                if (Xadd) v += al * Xadd[(long long)bz * zX + row * ldx + col + c];
                vals[c] = v;
            }
            float4 o;
            o.x = vals[0]; o.y = vals[1]; o.z = vals[2]; o.w = vals[3];
            *(float4*)(C + (long long)bz * zC + row * ldc + col) = o;
        }
    }
}

// ---------------------------------------------------------------------------
// Causal softmax over one row of one head; P[j]=0 for j>i. In-place.
// grid = H*S blocks of 256.
// ---------------------------------------------------------------------------
__global__ __launch_bounds__(256) void softmax_causal(float* __restrict__ P)
{
    __shared__ float red[256];
    const int h = blockIdx.x >> 11;    // / 2048
    const int i = blockIdx.x & 2047;
    float* row = P + ((size_t)h * S + (size_t)i) * S;
    const int len = i + 1;
    const int tid = threadIdx.x;

    float m = -3.4e38f;
    for (int j = tid; j < len; j += 256) m = fmaxf(m, row[j]);
    red[tid] = m;
    __syncthreads();
    for (int s = 128; s > 0; s >>= 1) {
        if (tid < s) red[tid] = fmaxf(red[tid], red[tid + s]);
        __syncthreads();
    }
    m = red[0];
    __syncthreads();

    float sum = 0.0f;
    for (int j = tid; j < len; j += 256) {
        float e = expf(row[j] - m);
        row[j] = e;
        sum += e;
    }
    red[tid] = sum;
    __syncthreads();
    for (int s = 128; s > 0; s >>= 1) {
        if (tid < s) red[tid] += red[tid + s];
        __syncthreads();
    }
    const float inv = 1.0f / red[0];
    for (int j = tid; j < len; j += 256) row[j] *= inv;
    for (int j = len + tid; j < S; j += 256) row[j] = 0.0f;
}

// ---------------------------------------------------------------------------
// Transpose 2048x2048: out[d][s] = in[s][d]
// ---------------------------------------------------------------------------
__global__ void transpose_kernel(const float* __restrict__ in,
                                 float* __restrict__ out)
{
    __shared__ float tile[32][33];
    const int bx = blockIdx.x * 32;   // col block of input (d)
    const int by = blockIdx.y * 32;   // row block of input (s)
    const int tx = threadIdx.x, ty = threadIdx.y;
#pragma unroll
    for (int r = 0; r < 32; r += 8)
        tile[ty + r][tx] = in[(size_t)(by + ty + r) * D + bx + tx];
    __syncthreads();
#pragma unroll
    for (int r = 0; r < 32; r += 8)
        out[(size_t)(bx + ty + r) * S + by + tx] = tile[tx][ty + r];
}

// ---------------------------------------------------------------------------
// h = silu(g) * u, written over g
// ---------------------------------------------------------------------------
__global__ __launch_bounds__(256) void silu_mul_kernel(
    float* __restrict__ g, const float* __restrict__ u)
{
    const size_t idx = (size_t)blockIdx.x * 256 + threadIdx.x;
    const float gv = g[idx];
    const float sig = 1.0f / (1.0f + expf(-gv));
    g[idx] = gv * sig * u[idx];
}

// ---------------------------------------------------------------------------
// Launch
// ---------------------------------------------------------------------------
extern "C" void kernel_launch(void* const* d_in, const int* in_sizes, int n_in,
                              void* d_out, int out_size)
{
    (void)in_sizes; (void)n_in; (void)out_size;

    const float* x     = (const float*)d_in[0];
    const float* wn_a  = (const float*)d_in[1];
    const float* wn_m  = (const float*)d_in[2];
    const float* Wq    = (const float*)d_in[3];
    const float* sq    = (const float*)d_in[4];
    const float* Wk    = (const float*)d_in[5];
    const float* sk    = (const float*)d_in[6];
    const float* Wv    = (const float*)d_in[7];
    const float* sv    = (const float*)d_in[8];
    const float* Wo    = (const float*)d_in[9];
    const float* so    = (const float*)d_in[10];
    const float* Wg    = (const float*)d_in[11];
    const float* sg    = (const float*)d_in[12];
    const float* Wu    = (const float*)d_in[13];
    const float* su    = (const float*)d_in[14];
    const float* Wd    = (const float*)d_in[15];
    const float* sd    = (const float*)d_in[16];
    const float* alpha = (const float*)d_in[17];
    float* out = (float*)d_out;

    float *normed, *q, *k, *v, *vT, *attn, *x1, *scores, *gate, *up;
    cudaGetSymbolAddress((void**)&normed, g_normed);
    cudaGetSymbolAddress((void**)&q,      g_q);
    cudaGetSymbolAddress((void**)&k,      g_k);
    cudaGetSymbolAddress((void**)&v,      g_v);
    cudaGetSymbolAddress((void**)&vT,     g_vT);
    cudaGetSymbolAddress((void**)&attn,   g_attn);
    cudaGetSymbolAddress((void**)&x1,     g_x1);
    cudaGetSymbolAddress((void**)&scores, g_scores);
    cudaGetSymbolAddress((void**)&gate,   g_gate);
    cudaGetSymbolAddress((void**)&up,     g_up);

    const float inv_sqrt_dh = 0.08838834764831845f;  // 1/sqrt(128)

    // 1. normed = rmsnorm(x, norm_attn_w)
    rmsnorm_kernel<<<S, 256>>>(x, wn_a, normed);

    // 2. q/k/v = normed @ W^T * s
    gemm_nt<<<dim3(D / 128, S / 128, 1), 256>>>(
        normed, D, 0, Wq, D, 0, q, D, 0, D,
        sq, 1.0f, nullptr, 0, nullptr, 0, 0, nullptr, 0);
    gemm_nt<<<dim3(D / 128, S / 128, 1), 256>>>(
        normed, D, 0, Wk, D, 0, k, D, 0, D,
        sk, 1.0f, nullptr, 0, nullptr, 0, 0, nullptr, 0);
    gemm_nt<<<dim3(D / 128, S / 128, 1), 256>>>(
        normed, D, 0, Wv, D, 0, v, D, 0, D,
        sv, 1.0f, nullptr, 0, nullptr, 0, 0, nullptr, 0);

    // 3. vT[d][s] = v[s][d]
    transpose_kernel<<<dim3(D / 32, S / 32), dim3(32, 8)>>>(v, vT);

    // 4. scores[h][i][j] = q_h[i] . k_h[j] / sqrt(DH)  (lower-tri blocks only)
    gemm_nt<<<dim3(S / 128, S / 128, H), 256>>>(
        q, D, (long long)DH, k, D, (long long)DH,
        scores, S, (long long)S * S, DH,
        nullptr, inv_sqrt_dh, nullptr, 0, nullptr, 0, 0, nullptr, 1);

    // 5. causal softmax in-place
    softmax_causal<<<H * S, 256>>>(scores);

    // 6. attn[s][h*DH+d] = P_h @ v_h  + alpha[h] * normed_head
    gemm_nt<<<dim3(DH / 128, S / 128, H), 256>>>(
        scores, S, (long long)S * S, vT, S, (long long)DH * S,
        attn, D, (long long)DH, S,
        nullptr, 1.0f, nullptr, 0, normed, D, (long long)DH, alpha, 2);

    // 7. x1 = x + attn @ Wo^T * so
    gemm_nt<<<dim3(D / 128, S / 128, 1), 256>>>(
        attn, D, 0, Wo, D, 0, x1, D, 0, D,
        so, 1.0f, x, D, nullptr, 0, 0, nullptr, 0);

    // 8. normed = rmsnorm(x1, norm_mlp_w)
    rmsnorm_kernel<<<S, 256>>>(x1, wn_m, normed);

    // 9. gate / up projections
    gemm_nt<<<dim3(DFF / 128, S / 128, 1), 256>>>(
        normed, D, 0, Wg, D, 0, gate, DFF, 0, D,
        sg, 1.0f, nullptr, 0, nullptr, 0, 0, nullptr, 0);
    gemm_nt<<<dim3(DFF / 128, S / 128, 1), 256>>>(
        normed, D, 0, Wu, D, 0, up, DFF, 0, D,
        su, 1.0f, nullptr, 0, nullptr, 0, 0, nullptr, 0);

    // 10. gate = silu(gate) * up
    silu_mul_kernel<<<(S * DFF) / 256, 256>>>(gate, up);

    // 11. out = x1 + gate @ Wd^T * sd
    gemm_nt<<<dim3(D / 128, S / 128, 1), 256>>>(
        gate, DFF, 0, Wd, DFF, 0, out, D, 0, DFF,
        sd, 1.0f, x1, D, nullptr, 0, 0, nullptr, 0);
}

// round 4
// speedup vs baseline: 3.0767x; 3.0767x over previous
#include <cuda_runtime.h>
#include <cuda_bf16.h>
#include <cstdint>
#include <math.h>

#define S   2048
#define D   2048
#define DFF 8192
#define H   16
#define DH  128

// ---------------------------------------------------------------------------
// Scratch (device globals; no allocation allowed)
// ---------------------------------------------------------------------------
__device__ float g_normed[(size_t)S * D];
__device__ float g_q[(size_t)S * D];
__device__ float g_k[(size_t)S * D];
__device__ float g_v[(size_t)S * D];
__device__ float g_vT[(size_t)S * D];          // [D][S]
__device__ float g_attn[(size_t)S * D];
__device__ float g_x1[(size_t)S * D];
__device__ float g_scores[(size_t)H * S * S];  // 268 MB
__device__ float g_gate[(size_t)S * DFF];
__device__ float g_up[(size_t)S * DFF];

__device__ __nv_bfloat16 g_wq_bf[(size_t)D * D];
__device__ __nv_bfloat16 g_wk_bf[(size_t)D * D];
__device__ __nv_bfloat16 g_wv_bf[(size_t)D * D];
__device__ __nv_bfloat16 g_wo_bf[(size_t)D * D];
__device__ __nv_bfloat16 g_wg_bf[(size_t)DFF * D];
__device__ __nv_bfloat16 g_wu_bf[(size_t)DFF * D];
__device__ __nv_bfloat16 g_wd_bf[(size_t)D * DFF];
__device__ __nv_bfloat16 g_ah[(size_t)S * DFF];   // activation hi
__device__ __nv_bfloat16 g_al[(size_t)S * DFF];   // activation lo

// ---------------------------------------------------------------------------
// helpers
// ---------------------------------------------------------------------------
__device__ __forceinline__ uint32_t smem_u32(const void* p) {
    uint32_t a;
    asm("{ .reg .u64 t; cvta.to.shared.u64 t, %1; cvt.u32.u64 %0, t; }"
        : "=r"(a) : "l"(p));
    return a;
}

// ---------------------------------------------------------------------------
// Tensor-core GEMM via mma.sync (sm_80+ ISA; works on plain sm_100 target)
// C[M,N] = scale * (Ah+Al)[M,K] @ Bw[N,K]^T (+ R)
// CTA tile 128x128, BK=32, 8 warps (2x4), warp tile 64x32.
// SMEM stage = Ah(8K) + Al(8K) + B(8K) = 24 KB, double-buffered (48 KB).
// Swizzle: 16B chunk' = chunk ^ ((row>>1)&3)  -> conflict-free STS + ldmatrix.
// ---------------------------------------------------------------------------
#define TILE_B   8192
#define STAGE_B  (3 * TILE_B)
#define MMA_SMEM (2 * STAGE_B)

__device__ __forceinline__ void cp_tile(
    uint32_t s_tile, const __nv_bfloat16* __restrict__ g,
    int row0, int ld, int k0, int tid)
{
#pragma unroll
    for (int i = 0; i < 2; i++) {
        const int idx = tid + i * 256;      // 0..511
        const int r   = idx >> 2;           // row 0..127
        const int ck  = idx & 3;            // 16B chunk 0..3
        const void* src = g + (size_t)(row0 + r) * ld + k0 + ck * 8;
        const uint32_t dst = s_tile + r * 64 + (((ck ^ ((r >> 1) & 3))) << 4);
        asm volatile("cp.async.cg.shared.global [%0], [%1], 16;"
                     :: "r"(dst), "l"(src));
    }
}

__device__ __forceinline__ uint32_t sw_addr(uint32_t s_tile, int row, int ck) {
    return s_tile + row * 64 + ((ck ^ ((row >> 1) & 3)) << 4);
}

__global__ __launch_bounds__(256)
void mma_gemm(const __nv_bfloat16* __restrict__ Ah,
              const __nv_bfloat16* __restrict__ Al,
              const __nv_bfloat16* __restrict__ Bw,
              float* __restrict__ C, int Ktot, int ldc,
              const float* __restrict__ scale,
              const float* __restrict__ R)
{
    extern __shared__ char smem[];
    const uint32_t sbase = smem_u32(smem);
    const int tid = threadIdx.x;
    const int l   = tid & 31;
    const int w   = tid >> 5;
    const int wm  = w >> 2;          // 0..1  (64-row slab)
    const int wn  = w & 3;           // 0..3  (32-col slab)
    const int bm  = blockIdx.y;
    const int bn  = blockIdx.x;
    const int rowA0 = bm * 128;
    const int rowB0 = bn * 128;

    float acc[4][4][4];
#pragma unroll
    for (int i = 0; i < 4; i++)
#pragma unroll
        for (int j = 0; j < 4; j++)
#pragma unroll
            for (int c = 0; c < 4; c++) acc[i][j][c] = 0.0f;

    const int nc = Ktot >> 5;     // K chunks of 32

    // prologue: stage 0
    cp_tile(sbase,              Ah, rowA0, Ktot, 0, tid);
    cp_tile(sbase + TILE_B,     Al, rowA0, Ktot, 0, tid);
    cp_tile(sbase + 2 * TILE_B, Bw, rowB0, Ktot, 0, tid);
    asm volatile("cp.async.commit_group;");

    for (int c = 0; c < nc; c++) {
        if (c + 1 < nc) {
            const uint32_t nb = sbase + ((c + 1) & 1) * STAGE_B;
            const int k0 = (c + 1) * 32;
            cp_tile(nb,              Ah, rowA0, Ktot, k0, tid);
            cp_tile(nb + TILE_B,     Al, rowA0, Ktot, k0, tid);
            cp_tile(nb + 2 * TILE_B, Bw, rowB0, Ktot, k0, tid);
            asm volatile("cp.async.commit_group;");
            asm volatile("cp.async.wait_group 1;");
        } else {
            asm volatile("cp.async.wait_group 0;");
        }
        __syncthreads();

        const uint32_t st  = sbase + (c & 1) * STAGE_B;
        const uint32_t sA0 = st;              // Ah
        const uint32_t sA1 = st + TILE_B;     // Al
        const uint32_t sB  = st + 2 * TILE_B;

#pragma unroll
        for (int ks = 0; ks < 2; ks++) {
            // B frags: 4 n-frags of k16 x n8.
            // B tile in smem is [n rows][k cols] (k contiguous), which is
            // exactly the mma B fragment layout under a NON-transposed
            // ldmatrix: thread l gets M[n=l/4][k=(l%4)*2+j].
            uint32_t bf[4][2];
#pragma unroll
            for (int nf = 0; nf < 4; nf++) {
                const int nrow = wn * 32 + nf * 8 + (l & 7);
                const int ck   = ks * 2 + ((l >> 3) & 1);
                asm volatile(
                    "ldmatrix.sync.aligned.m8n8.x2.shared.b16 {%0,%1}, [%2];"
                    : "=r"(bf[nf][0]), "=r"(bf[nf][1])
                    : "r"(sw_addr(sB, nrow, ck)));
            }
#pragma unroll
            for (int pass = 0; pass < 2; pass++) {
                const uint32_t sA = pass ? sA1 : sA0;
                uint32_t af[4][4];
#pragma unroll
                for (int mf = 0; mf < 4; mf++) {
                    const int arow = wm * 64 + mf * 16 + (l & 15);
                    const int ck   = ks * 2 + (l >> 4);
                    asm volatile(
                        "ldmatrix.sync.aligned.m8n8.x4.shared.b16 {%0,%1,%2,%3}, [%4];"
                        : "=r"(af[mf][0]), "=r"(af[mf][1]),
                          "=r"(af[mf][2]), "=r"(af[mf][3])
                        : "r"(sw_addr(sA, arow, ck)));
                }
#pragma unroll
                for (int mf = 0; mf < 4; mf++)
#pragma unroll
                    for (int nf = 0; nf < 4; nf++) {
                        asm volatile(
                            "mma.sync.aligned.m16n8k16.row.col.f32.bf16.bf16.f32 "
                            "{%0,%1,%2,%3}, {%4,%5,%6,%7}, {%8,%9}, {%0,%1,%2,%3};"
                            : "+f"(acc[mf][nf][0]), "+f"(acc[mf][nf][1]),
                              "+f"(acc[mf][nf][2]), "+f"(acc[mf][nf][3])
                            : "r"(af[mf][0]), "r"(af[mf][1]),
                              "r"(af[mf][2]), "r"(af[mf][3]),
                              "r"(bf[nf][0]), "r"(bf[nf][1]));
                    }
            }
        }
        __syncthreads();
    }

    // epilogue
    const float sc = scale ? __ldg(scale) : 1.0f;
    const int qrow = l >> 2;
    const int qcol = (l & 3) * 2;

#pragma unroll
    for (int mf = 0; mf < 4; mf++) {
        const size_t r0 = (size_t)(bm * 128 + wm * 64 + mf * 16 + qrow);
#pragma unroll
        for (int nf = 0; nf < 4; nf++) {
            const size_t c0 = (size_t)(bn * 128 + wn * 32 + nf * 8 + qcol);
#pragma unroll
            for (int half = 0; half < 2; half++) {
                const size_t row = r0 + half * 8;
                float2 o;
                o.x = acc[mf][nf][half * 2 + 0] * sc;
                o.y = acc[mf][nf][half * 2 + 1] * sc;
                const size_t off = row * ldc + c0;
                if (R) {
                    const float2 rv = *(const float2*)(R + off);
                    o.x += rv.x; o.y += rv.y;
                }
                *(float2*)(C + off) = o;
            }
        }
    }
}

// ---------------------------------------------------------------------------
// Conversions
// ---------------------------------------------------------------------------
__global__ __launch_bounds__(256) void f32_to_bf16_kernel(
    const float* __restrict__ in, __nv_bfloat16* __restrict__ out, int n4)
{
    const int i = blockIdx.x * 256 + threadIdx.x;
    if (i >= n4) return;
    const float4 v = ((const float4*)in)[i];
    __nv_bfloat162 p0 = __floats2bfloat162_rn(v.x, v.y);
    __nv_bfloat162 p1 = __floats2bfloat162_rn(v.z, v.w);
    uint2 o;
    o.x = *(uint32_t*)&p0;
    o.y = *(uint32_t*)&p1;
    ((uint2*)out)[i] = o;
}

__global__ __launch_bounds__(256) void split_f32_kernel(
    const float* __restrict__ in, __nv_bfloat16* __restrict__ hi,
    __nv_bfloat16* __restrict__ lo, int n4)
{
    const int i = blockIdx.x * 256 + threadIdx.x;
    if (i >= n4) return;
    const float4 v = ((const float4*)in)[i];
    float a[4] = {v.x, v.y, v.z, v.w};
    __nv_bfloat16 h[4], lw[4];
#pragma unroll
    for (int j = 0; j < 4; j++) {
        h[j] = __float2bfloat16_rn(a[j]);
        lw[j] = __float2bfloat16_rn(a[j] - __bfloat162float(h[j]));
    }
    __nv_bfloat162 h0 = __nv_bfloat162(h[0], h[1]), h1 = __nv_bfloat162(h[2], h[3]);
    __nv_bfloat162 l0 = __nv_bfloat162(lw[0], lw[1]), l1 = __nv_bfloat162(lw[2], lw[3]);
    uint2 ho, lo_;
    ho.x = *(uint32_t*)&h0; ho.y = *(uint32_t*)&h1;
    lo_.x = *(uint32_t*)&l0; lo_.y = *(uint32_t*)&l1;
    ((uint2*)hi)[i] = ho;
    ((uint2*)lo)[i] = lo_;
}

// ---------------------------------------------------------------------------
// RMSNorm
// ---------------------------------------------------------------------------
__global__ __launch_bounds__(256) void rmsnorm_kernel(
    const float* __restrict__ x, const float* __restrict__ w,
    float* __restrict__ out)
{
    __shared__ float red[256];
    const int r = blockIdx.x;
    const int tid = threadIdx.x;
    const float* xr = x + (size_t)r * D;

    float ss = 0.0f;
    for (int j = tid; j < D; j += 256) { float v = xr[j]; ss += v * v; }
    red[tid] = ss;
    __syncthreads();
    for (int s = 128; s > 0; s >>= 1) {
        if (tid < s) red[tid] += red[tid + s];
        __syncthreads();
    }
    const float sc = rsqrtf(red[0] / (float)D + 1e-6f);
    float* orow = out + (size_t)r * D;
    for (int j = tid; j < D; j += 256)
        orow[j] = xr[j] * sc * w[j];
}

// ---------------------------------------------------------------------------
// SIMT GEMM (attention only): C = s*A@B^T (+alpha*Xadd), causal modes
// ---------------------------------------------------------------------------
__global__ __launch_bounds__(256) void gemm_nt(
    const float* __restrict__ A, int lda, long long zA,
    const float* __restrict__ B, int ldb, long long zB,
    float* __restrict__ C, int ldc, long long zC,
    int K,
    const float* __restrict__ scale_ptr, float scale_const,
    const float* __restrict__ R, int ldr,
    const float* __restrict__ Xadd, int ldx, long long zX,
    const float* __restrict__ alpha,
    int causal_mode)
{
    const int bm = blockIdx.y;
    const int bn = blockIdx.x;
    const int bz = blockIdx.z;

    if (causal_mode == 1 && bn > bm) return;
    const int kEnd = (causal_mode == 2) ? min(K, (bm + 1) * 128) : K;

    __shared__ __align__(16) float As[8][128];
    __shared__ __align__(16) float Bs[8][128];

    const int tid = threadIdx.x;
    const int lr  = tid >> 1;
    const int lq  = (tid & 1) * 4;
    const int tx4 = (tid & 15) * 4;
    const int ty4 = (tid >> 4) * 4;

    const float* Ab = A + (long long)bz * zA + (size_t)(bm * 128) * lda;
    const float* Bb = B + (long long)bz * zB + (size_t)(bn * 128) * ldb;

    float acc[8][8];
#pragma unroll
    for (int i = 0; i < 8; i++)
#pragma unroll
        for (int j = 0; j < 8; j++) acc[i][j] = 0.0f;

    for (int k0 = 0; k0 < kEnd; k0 += 8) {
        float4 av = *(const float4*)(Ab + (size_t)lr * lda + k0 + lq);
        float4 bv = *(const float4*)(Bb + (size_t)lr * ldb + k0 + lq);
        As[lq + 0][lr] = av.x; As[lq + 1][lr] = av.y;
        As[lq + 2][lr] = av.z; As[lq + 3][lr] = av.w;
        Bs[lq + 0][lr] = bv.x; Bs[lq + 1][lr] = bv.y;
        Bs[lq + 2][lr] = bv.z; Bs[lq + 3][lr] = bv.w;
        __syncthreads();

#pragma unroll
        for (int kk = 0; kk < 8; kk++) {
            float4 a0 = *(const float4*)&As[kk][ty4];
            float4 a1 = *(const float4*)&As[kk][ty4 + 64];
            float4 b0 = *(const float4*)&Bs[kk][tx4];
            float4 b1 = *(const float4*)&Bs[kk][tx4 + 64];
            float a[8] = {a0.x, a0.y, a0.z, a0.w, a1.x, a1.y, a1.z, a1.w};
            float b[8] = {b0.x, b0.y, b0.z, b0.w, b1.x, b1.y, b1.z, b1.w};
#pragma unroll
            for (int i = 0; i < 8; i++)
#pragma unroll
                for (int j = 0; j < 8; j++)
                    acc[i][j] += a[i] * b[j];
        }
        __syncthreads();
    }

    float s = scale_const;
    if (scale_ptr) s *= *scale_ptr;
    const float al = alpha ? alpha[bz] : 0.0f;

#pragma unroll
    for (int i = 0; i < 8; i++) {
        const int ri = (i < 4) ? (ty4 + i) : (64 + ty4 + i - 4);
        const size_t row = (size_t)(bm * 128 + ri);
#pragma unroll
        for (int jb = 0; jb < 2; jb++) {
            const int cj = (jb == 0) ? tx4 : (64 + tx4);
            const size_t col = (size_t)(bn * 128 + cj);
            float vals[4];
#pragma unroll
            for (int c = 0; c < 4; c++) {
                float v = acc[i][jb * 4 + c] * s;
                if (R)    v += R[row * ldr + col + c];
                if (Xadd) v += al * Xadd[(long long)bz * zX + row * ldx + col + c];
                vals[c] = v;
            }
            float4 o;
            o.x = vals[0]; o.y = vals[1]; o.z = vals[2]; o.w = vals[3];
            *(float4*)(C + (long long)bz * zC + row * ldc + col) = o;
        }
    }
}

// ---------------------------------------------------------------------------
// Causal softmax
// ---------------------------------------------------------------------------
__global__ __launch_bounds__(256) void softmax_causal(float* __restrict__ P)
{
    __shared__ float red[256];
    const int h = blockIdx.x >> 11;
    const int i = blockIdx.x & 2047;
    float* row = P + ((size_t)h * S + (size_t)i) * S;
    const int len = i + 1;
    const int tid = threadIdx.x;

    float m = -3.4e38f;
    for (int j = tid; j < len; j += 256) m = fmaxf(m, row[j]);
    red[tid] = m;
    __syncthreads();
    for (int s = 128; s > 0; s >>= 1) {
        if (tid < s) red[tid] = fmaxf(red[tid], red[tid + s]);
        __syncthreads();
    }
    m = red[0];
    __syncthreads();

    float sum = 0.0f;
    for (int j = tid; j < len; j += 256) {
        float e = expf(row[j] - m);
        row[j] = e;
        sum += e;
    }
    red[tid] = sum;
    __syncthreads();
    for (int s = 128; s > 0; s >>= 1) {
        if (tid < s) red[tid] += red[tid + s];
        __syncthreads();
    }
    const float inv = 1.0f / red[0];
    for (int j = tid; j < len; j += 256) row[j] *= inv;
    for (int j = len + tid; j < S; j += 256) row[j] = 0.0f;
}

// ---------------------------------------------------------------------------
// Transpose 2048x2048
// ---------------------------------------------------------------------------
__global__ void transpose_kernel(const float* __restrict__ in,
                                 float* __restrict__ out)
{
    __shared__ float tile[32][33];
    const int bx = blockIdx.x * 32;
    const int by = blockIdx.y * 32;
    const int tx = threadIdx.x, ty = threadIdx.y;
#pragma unroll
    for (int r = 0; r < 32; r += 8)
        tile[ty + r][tx] = in[(size_t)(by + ty + r) * D + bx + tx];
    __syncthreads();
#pragma unroll
    for (int r = 0; r < 32; r += 8)
        out[(size_t)(bx + ty + r) * S + by + tx] = tile[tx][ty + r];
}

// ---------------------------------------------------------------------------
// h = silu(g) * u
// ---------------------------------------------------------------------------
__global__ __launch_bounds__(256) void silu_mul_kernel(
    float* __restrict__ g, const float* __restrict__ u)
{
    const size_t idx = (size_t)blockIdx.x * 256 + threadIdx.x;
    const float gv = g[idx];
    const float sig = 1.0f / (1.0f + expf(-gv));
    g[idx] = gv * sig * u[idx];
}

// ---------------------------------------------------------------------------
// Launch
// ---------------------------------------------------------------------------
extern "C" void kernel_launch(void* const* d_in, const int* in_sizes, int n_in,
                              void* d_out, int out_size)
{
    (void)in_sizes; (void)n_in; (void)out_size;

    const float* x     = (const float*)d_in[0];
    const float* wn_a  = (const float*)d_in[1];
    const float* wn_m  = (const float*)d_in[2];
    const float* Wq    = (const float*)d_in[3];
    const float* sq    = (const float*)d_in[4];
    const float* Wk    = (const float*)d_in[5];
    const float* sk    = (const float*)d_in[6];
    const float* Wv    = (const float*)d_in[7];
    const float* sv    = (const float*)d_in[8];
    const float* Wo    = (const float*)d_in[9];
    const float* so    = (const float*)d_in[10];
    const float* Wg    = (const float*)d_in[11];
    const float* sg    = (const float*)d_in[12];
    const float* Wu    = (const float*)d_in[13];
    const float* su    = (const float*)d_in[14];
    const float* Wd    = (const float*)d_in[15];
    const float* sd    = (const float*)d_in[16];
    const float* alpha = (const float*)d_in[17];
    float* out = (float*)d_out;

    float *normed, *q, *k, *v, *vT, *attn, *x1, *scores, *gate, *up;
    cudaGetSymbolAddress((void**)&normed, g_normed);
    cudaGetSymbolAddress((void**)&q,      g_q);
    cudaGetSymbolAddress((void**)&k,      g_k);
    cudaGetSymbolAddress((void**)&v,      g_v);
    cudaGetSymbolAddress((void**)&vT,     g_vT);
    cudaGetSymbolAddress((void**)&attn,   g_attn);
    cudaGetSymbolAddress((void**)&x1,     g_x1);
    cudaGetSymbolAddress((void**)&scores, g_scores);
    cudaGetSymbolAddress((void**)&gate,   g_gate);
    cudaGetSymbolAddress((void**)&up,     g_up);

    __nv_bfloat16 *wq, *wk, *wv, *wo, *wg, *wu, *wd, *ah, *al;
    cudaGetSymbolAddress((void**)&wq, g_wq_bf);
    cudaGetSymbolAddress((void**)&wk, g_wk_bf);
    cudaGetSymbolAddress((void**)&wv, g_wv_bf);
    cudaGetSymbolAddress((void**)&wo, g_wo_bf);
    cudaGetSymbolAddress((void**)&wg, g_wg_bf);
    cudaGetSymbolAddress((void**)&wu, g_wu_bf);
    cudaGetSymbolAddress((void**)&wd, g_wd_bf);
    cudaGetSymbolAddress((void**)&ah, g_ah);
    cudaGetSymbolAddress((void**)&al, g_al);

    cudaFuncSetAttribute(mma_gemm, cudaFuncAttributeMaxDynamicSharedMemorySize,
                         MMA_SMEM);

    const float inv_sqrt_dh = 0.08838834764831845f;

    // 0. weights -> bf16 (exact for ternary)
    const int nDD = D * D / 4, nFD = DFF * D / 4;
    f32_to_bf16_kernel<<<(nDD + 255) / 256, 256>>>(Wq, wq, nDD);
    f32_to_bf16_kernel<<<(nDD + 255) / 256, 256>>>(Wk, wk, nDD);
    f32_to_bf16_kernel<<<(nDD + 255) / 256, 256>>>(Wv, wv, nDD);
    f32_to_bf16_kernel<<<(nDD + 255) / 256, 256>>>(Wo, wo, nDD);
    f32_to_bf16_kernel<<<(nFD + 255) / 256, 256>>>(Wg, wg, nFD);
    f32_to_bf16_kernel<<<(nFD + 255) / 256, 256>>>(Wu, wu, nFD);
    f32_to_bf16_kernel<<<(nFD + 255) / 256, 256>>>(Wd, wd, nFD);

    // 1. rmsnorm + hi/lo split
    rmsnorm_kernel<<<S, 256>>>(x, wn_a, normed);
    split_f32_kernel<<<(S * D / 4 + 255) / 256, 256>>>(normed, ah, al, S * D / 4);

    // 2. q/k/v projections (tensor cores)
    mma_gemm<<<dim3(D / 128, S / 128), 256, MMA_SMEM>>>(ah, al, wq, q, D, D, sq, nullptr);
    mma_gemm<<<dim3(D / 128, S / 128), 256, MMA_SMEM>>>(ah, al, wk, k, D, D, sk, nullptr);
    mma_gemm<<<dim3(D / 128, S / 128), 256, MMA_SMEM>>>(ah, al, wv, v, D, D, sv, nullptr);

    // 3. vT
    transpose_kernel<<<dim3(D / 32, S / 32), dim3(32, 8)>>>(v, vT);

    // 4. scores (lower-tri blocks)
    gemm_nt<<<dim3(S / 128, S / 128, H), 256>>>(
        q, D, (long long)DH, k, D, (long long)DH,
        scores, S, (long long)S * S, DH,
        nullptr, inv_sqrt_dh, nullptr, 0, nullptr, 0, 0, nullptr, 1);

    // 5. softmax
    softmax_causal<<<H * S, 256>>>(scores);

    // 6. PV + alpha*normed
    gemm_nt<<<dim3(DH / 128, S / 128, H), 256>>>(
        scores, S, (long long)S * S, vT, S, (long long)DH * S,
        attn, D, (long long)DH, S,
        nullptr, 1.0f, nullptr, 0, normed, D, (long long)DH, alpha, 2);

    // 7. x1 = x + attn @ Wo^T * so
    split_f32_kernel<<<(S * D / 4 + 255) / 256, 256>>>(attn, ah, al, S * D / 4);
    mma_gemm<<<dim3(D / 128, S / 128), 256, MMA_SMEM>>>(ah, al, wo, x1, D, D, so, x);

    // 8. mlp norm + split
    rmsnorm_kernel<<<S, 256>>>(x1, wn_m, normed);
    split_f32_kernel<<<(S * D / 4 + 255) / 256, 256>>>(normed, ah, al, S * D / 4);

    // 9. gate / up
    mma_gemm<<<dim3(DFF / 128, S / 128), 256, MMA_SMEM>>>(ah, al, wg, gate, D, DFF, sg, nullptr);
    mma_gemm<<<dim3(DFF / 128, S / 128), 256, MMA_SMEM>>>(ah, al, wu, up, D, DFF, su, nullptr);

    // 10. gate = silu(gate) * up; split
    silu_mul_kernel<<<(S * DFF) / 256, 256>>>(gate, up);
    split_f32_kernel<<<(S * DFF / 4 + 255) / 256, 256>>>(gate, ah, al, S * DFF / 4);

    // 11. out = x1 + h @ Wd^T * sd
    mma_gemm<<<dim3(D / 128, S / 128), 256, MMA_SMEM>>>(ah, al, wd, out, DFF, D, sd, x1);
}

// round 5
// speedup vs baseline: 4.5110x; 1.4662x over previous
#include <cuda_runtime.h>
#include <cuda_bf16.h>
#include <cstdint>
#include <math.h>

#define S   2048
#define D   2048
#define DFF 8192
#define H   16
#define DH  128

// ---------------------------------------------------------------------------
// Scratch (device globals; no allocation allowed)
// ---------------------------------------------------------------------------
__device__ float g_normed[(size_t)S * D];
__device__ float g_x1[(size_t)S * D];
__device__ float g_gate[(size_t)S * DFF];
__device__ float g_up[(size_t)S * DFF];

__device__ __nv_bfloat16 g_qb[(size_t)S * D];
__device__ __nv_bfloat16 g_kb[(size_t)S * D];
__device__ __nv_bfloat16 g_vb[(size_t)S * D];

__device__ __nv_bfloat16 g_wq_bf[(size_t)D * D];
__device__ __nv_bfloat16 g_wk_bf[(size_t)D * D];
__device__ __nv_bfloat16 g_wv_bf[(size_t)D * D];
__device__ __nv_bfloat16 g_wo_bf[(size_t)D * D];
__device__ __nv_bfloat16 g_wg_bf[(size_t)DFF * D];
__device__ __nv_bfloat16 g_wu_bf[(size_t)DFF * D];
__device__ __nv_bfloat16 g_wd_bf[(size_t)D * DFF];
__device__ __nv_bfloat16 g_ah[(size_t)S * DFF];   // activation hi
__device__ __nv_bfloat16 g_al[(size_t)S * DFF];   // activation lo

// ---------------------------------------------------------------------------
// helpers
// ---------------------------------------------------------------------------
__device__ __forceinline__ uint32_t smem_u32(const void* p) {
    uint32_t a;
    asm("{ .reg .u64 t; cvta.to.shared.u64 t, %1; cvt.u32.u64 %0, t; }"
        : "=r"(a) : "l"(p));
    return a;
}

__device__ __forceinline__ uint32_t packbf(float x, float y) {
    __nv_bfloat162 t = __floats2bfloat162_rn(x, y);
    return *(uint32_t*)&t;
}

__device__ __forceinline__ void mma16816(float* c, const uint32_t* a,
                                         uint32_t b0, uint32_t b1) {
    asm volatile(
        "mma.sync.aligned.m16n8k16.row.col.f32.bf16.bf16.f32 "
        "{%0,%1,%2,%3}, {%4,%5,%6,%7}, {%8,%9}, {%0,%1,%2,%3};"
        : "+f"(c[0]), "+f"(c[1]), "+f"(c[2]), "+f"(c[3])
        : "r"(a[0]), "r"(a[1]), "r"(a[2]), "r"(a[3]), "r"(b0), "r"(b1));
}

// ---------------------------------------------------------------------------
// Weight GEMM via mma.sync.  C = sc*(Ah+Al)@Bw^T (+R), f32 or bf16 output.
// CTA 128x128, BK=32, 8 warps (2x4), warp tile 64x32, 3-stage cp.async.
// Tile rows = 64B; swizzle: ck ^= (row>>1)&3.
// ---------------------------------------------------------------------------
#define TILE_B   8192
#define STAGE_B  (3 * TILE_B)
#define MMA_SMEM (3 * STAGE_B)

__device__ __forceinline__ void cp_tile(
    uint32_t s_tile, const __nv_bfloat16* __restrict__ g,
    int row0, int ld, int k0, int tid)
{
#pragma unroll
    for (int i = 0; i < 2; i++) {
        const int idx = tid + i * 256;      // 0..511
        const int r   = idx >> 2;           // row 0..127
        const int ck  = idx & 3;            // 16B chunk 0..3
        const void* src = g + (size_t)(row0 + r) * ld + k0 + ck * 8;
        const uint32_t dst = s_tile + r * 64 + (((ck ^ ((r >> 1) & 3))) << 4);
        asm volatile("cp.async.cg.shared.global [%0], [%1], 16;"
                     :: "r"(dst), "l"(src));
    }
}

__device__ __forceinline__ uint32_t sw_addr(uint32_t s_tile, int row, int ck) {
    return s_tile + row * 64 + ((ck ^ ((row >> 1) & 3)) << 4);
}

__device__ __forceinline__ void load_stage(
    uint32_t stg, const __nv_bfloat16* Ah, const __nv_bfloat16* Al,
    const __nv_bfloat16* Bw, int rowA0, int rowB0, int Ktot, int k0, int tid)
{
    cp_tile(stg,              Ah, rowA0, Ktot, k0, tid);
    cp_tile(stg + TILE_B,     Al, rowA0, Ktot, k0, tid);
    cp_tile(stg + 2 * TILE_B, Bw, rowB0, Ktot, k0, tid);
    asm volatile("cp.async.commit_group;");
}

__global__ __launch_bounds__(256)
void mma_gemm(const __nv_bfloat16* __restrict__ Ah,
              const __nv_bfloat16* __restrict__ Al,
              const __nv_bfloat16* __restrict__ Bw,
              float* __restrict__ Cf,
              __nv_bfloat16* __restrict__ Cb,
              int Ktot, int ldc,
              const float* __restrict__ scale, float scale_const,
              const float* __restrict__ R)
{
    extern __shared__ char smem[];
    const uint32_t sbase = smem_u32(smem);
    const int tid = threadIdx.x;
    const int l   = tid & 31;
    const int w   = tid >> 5;
    const int wm  = w >> 2;
    const int wn  = w & 3;
    const int bm  = blockIdx.y;
    const int bn  = blockIdx.x;
    const int rowA0 = bm * 128;
    const int rowB0 = bn * 128;

    float acc[4][4][4];
#pragma unroll
    for (int i = 0; i < 4; i++)
#pragma unroll
        for (int j = 0; j < 4; j++)
#pragma unroll
            for (int c = 0; c < 4; c++) acc[i][j][c] = 0.0f;

    const int nc = Ktot >> 5;

    load_stage(sbase,           Ah, Al, Bw, rowA0, rowB0, Ktot, 0,  tid);
    load_stage(sbase + STAGE_B, Ah, Al, Bw, rowA0, rowB0, Ktot, 32, tid);

    for (int c = 0; c < nc; c++) {
        if (c + 2 < nc) {
            load_stage(sbase + ((c + 2) % 3) * STAGE_B, Ah, Al, Bw,
                       rowA0, rowB0, Ktot, (c + 2) * 32, tid);
            asm volatile("cp.async.wait_group 2;");
        } else if (c + 1 < nc) {
            asm volatile("cp.async.wait_group 1;");
        } else {
            asm volatile("cp.async.wait_group 0;");
        }
        __syncthreads();

        const uint32_t st  = sbase + (c % 3) * STAGE_B;
        const uint32_t sA0 = st;
        const uint32_t sA1 = st + TILE_B;
        const uint32_t sB  = st + 2 * TILE_B;

#pragma unroll
        for (int ks = 0; ks < 2; ks++) {
            uint32_t bf[4][2];
#pragma unroll
            for (int nf = 0; nf < 4; nf++) {
                const int nrow = wn * 32 + nf * 8 + (l & 7);
                const int ck   = ks * 2 + ((l >> 3) & 1);
                asm volatile(
                    "ldmatrix.sync.aligned.m8n8.x2.shared.b16 {%0,%1}, [%2];"
                    : "=r"(bf[nf][0]), "=r"(bf[nf][1])
                    : "r"(sw_addr(sB, nrow, ck)));
            }
#pragma unroll
            for (int pass = 0; pass < 2; pass++) {
                const uint32_t sA = pass ? sA1 : sA0;
                uint32_t af[4][4];
#pragma unroll
                for (int mf = 0; mf < 4; mf++) {
                    const int arow = wm * 64 + mf * 16 + (l & 15);
                    const int ck   = ks * 2 + (l >> 4);
                    asm volatile(
                        "ldmatrix.sync.aligned.m8n8.x4.shared.b16 {%0,%1,%2,%3}, [%4];"
                        : "=r"(af[mf][0]), "=r"(af[mf][1]),
                          "=r"(af[mf][2]), "=r"(af[mf][3])
                        : "r"(sw_addr(sA, arow, ck)));
                }
#pragma unroll
                for (int mf = 0; mf < 4; mf++)
#pragma unroll
                    for (int nf = 0; nf < 4; nf++)
                        mma16816(acc[mf][nf], af[mf], bf[nf][0], bf[nf][1]);
            }
        }
        __syncthreads();
    }

    float sc = scale_const;
    if (scale) sc *= __ldg(scale);
    const int qrow = l >> 2;
    const int qcol = (l & 3) * 2;

#pragma unroll
    for (int mf = 0; mf < 4; mf++) {
        const size_t r0 = (size_t)(bm * 128 + wm * 64 + mf * 16 + qrow);
#pragma unroll
        for (int nf = 0; nf < 4; nf++) {
            const size_t c0 = (size_t)(bn * 128 + wn * 32 + nf * 8 + qcol);
#pragma unroll
            for (int half = 0; half < 2; half++) {
                const size_t row = r0 + half * 8;
                const size_t off = row * ldc + c0;
                float ox = acc[mf][nf][half * 2 + 0] * sc;
                float oy = acc[mf][nf][half * 2 + 1] * sc;
                if (Cb) {
                    *(uint32_t*)(Cb + off) = packbf(ox, oy);
                } else {
                    if (R) {
                        const float2 rv = *(const float2*)(R + off);
                        ox += rv.x; oy += rv.y;
                    }
                    float2 o; o.x = ox; o.y = oy;
                    *(float2*)(Cf + off) = o;
                }
            }
        }
    }
}

// ---------------------------------------------------------------------------
// Flash attention (bf16 tensor cores, online softmax).
// grid = (S/128, H), block = 256 (8 warps, 16 rows each).
// Tiles: 128 rows x 256B; swizzle ck' = ((ck&7)^(row&7)) | (ck&8).
// Q/K stored row-major [S][D]; V B-frag via ldmatrix.trans.
// Epilogue: out = O/l + alpha[h]*normed, written as hi/lo bf16 split.
// ---------------------------------------------------------------------------
#define FL_STAGE 65536
#define FL_SMEM  (2 * FL_STAGE)

__device__ __forceinline__ uint32_t sw256(uint32_t base, int row, int ck) {
    return base + row * 256 + (((((ck & 7) ^ (row & 7))) | (ck & 8)) << 4);
}

__device__ __forceinline__ void cp_tile256(
    uint32_t s_tile, const __nv_bfloat16* __restrict__ g,
    int row0, int col0, int tid)
{
#pragma unroll
    for (int i = 0; i < 8; i++) {
        const int idx = tid + i * 256;
        const int r  = idx >> 4;
        const int ck = idx & 15;
        const void* src = g + (size_t)(row0 + r) * D + col0 + ck * 8;
        asm volatile("cp.async.cg.shared.global [%0], [%1], 16;"
                     :: "r"(sw256(s_tile, r, ck)), "l"(src));
    }
}

__global__ __launch_bounds__(256)
void flash_attn(const __nv_bfloat16* __restrict__ Qb,
                const __nv_bfloat16* __restrict__ Kb,
                const __nv_bfloat16* __restrict__ Vb,
                const float* __restrict__ normed,
                const float* __restrict__ alpha,
                __nv_bfloat16* __restrict__ outh,
                __nv_bfloat16* __restrict__ outl)
{
    extern __shared__ char smem[];
    const uint32_t sbase = smem_u32(smem);
    const int tid = threadIdx.x;
    const int l   = tid & 31;
    const int w   = tid >> 5;
    const int bq  = blockIdx.x;
    const int h   = blockIdx.y;
    const int col0 = h * DH;

    // Q tile -> stage0 smem -> registers
    cp_tile256(sbase, Qb, bq * 128, col0, tid);
    asm volatile("cp.async.commit_group;");
    asm volatile("cp.async.wait_group 0;");
    __syncthreads();

    uint32_t qf[8][4];
#pragma unroll
    for (int kk = 0; kk < 8; kk++) {
        const int r  = w * 16 + (l & 15);
        const int ck = kk * 2 + (l >> 4);
        asm volatile("ldmatrix.sync.aligned.m8n8.x4.shared.b16 {%0,%1,%2,%3}, [%4];"
            : "=r"(qf[kk][0]), "=r"(qf[kk][1]), "=r"(qf[kk][2]), "=r"(qf[kk][3])
            : "r"(sw256(sbase, r, ck)));
    }
    __syncthreads();

    float oacc[16][4];
#pragma unroll
    for (int i = 0; i < 16; i++)
#pragma unroll
        for (int j = 0; j < 4; j++) oacc[i][j] = 0.0f;
    float m0 = -1e30f, m1 = -1e30f, l0 = 0.0f, l1 = 0.0f;

    // prologue: KV block 0 -> stage0
    cp_tile256(sbase,         Kb, 0, col0, tid);
    cp_tile256(sbase + 32768, Vb, 0, col0, tid);
    asm volatile("cp.async.commit_group;");

    for (int kb = 0; kb <= bq; kb++) {
        if (kb + 1 <= bq) {
            const uint32_t nb = sbase + ((kb + 1) & 1) * FL_STAGE;
            cp_tile256(nb,         Kb, (kb + 1) * 128, col0, tid);
            cp_tile256(nb + 32768, Vb, (kb + 1) * 128, col0, tid);
            asm volatile("cp.async.commit_group;");
            asm volatile("cp.async.wait_group 1;");
        } else {
            asm volatile("cp.async.wait_group 0;");
        }
        __syncthreads();

        const uint32_t sK = sbase + (kb & 1) * FL_STAGE;
        const uint32_t sV = sK + 32768;

        // ---- S = Q @ K^T
        float sacc[16][4];
#pragma unroll
        for (int i = 0; i < 16; i++)
#pragma unroll
            for (int j = 0; j < 4; j++) sacc[i][j] = 0.0f;

#pragma unroll
        for (int kk = 0; kk < 8; kk++) {
#pragma unroll
            for (int p = 0; p < 8; p++) {
                uint32_t b[4];
                const int r  = p * 16 + ((l >> 4) << 3) + (l & 7);
                const int ck = kk * 2 + ((l >> 3) & 1);
                asm volatile(
                    "ldmatrix.sync.aligned.m8n8.x4.shared.b16 {%0,%1,%2,%3}, [%4];"
                    : "=r"(b[0]), "=r"(b[1]), "=r"(b[2]), "=r"(b[3])
                    : "r"(sw256(sK, r, ck)));
                mma16816(sacc[2 * p],     qf[kk], b[0], b[1]);
                mma16816(sacc[2 * p + 1], qf[kk], b[2], b[3]);
            }
        }

        // ---- causal mask on diagonal block (local coords: col > row)
        if (kb == bq) {
            const int r0 = w * 16 + (l >> 2);
#pragma unroll
            for (int nf = 0; nf < 16; nf++) {
                const int c0 = nf * 8 + (l & 3) * 2;
                if (c0     > r0)     sacc[nf][0] = -1e30f;
                if (c0 + 1 > r0)     sacc[nf][1] = -1e30f;
                if (c0     > r0 + 8) sacc[nf][2] = -1e30f;
                if (c0 + 1 > r0 + 8) sacc[nf][3] = -1e30f;
            }
        }

        // ---- online softmax stats
        float bm0 = -1e30f, bm1 = -1e30f;
#pragma unroll
        for (int nf = 0; nf < 16; nf++) {
            bm0 = fmaxf(bm0, fmaxf(sacc[nf][0], sacc[nf][1]));
            bm1 = fmaxf(bm1, fmaxf(sacc[nf][2], sacc[nf][3]));
        }
        bm0 = fmaxf(bm0, __shfl_xor_sync(0xFFFFFFFFu, bm0, 1));
        bm0 = fmaxf(bm0, __shfl_xor_sync(0xFFFFFFFFu, bm0, 2));
        bm1 = fmaxf(bm1, __shfl_xor_sync(0xFFFFFFFFu, bm1, 1));
        bm1 = fmaxf(bm1, __shfl_xor_sync(0xFFFFFFFFu, bm1, 2));

        const float nm0 = fmaxf(m0, bm0);
        const float nm1 = fmaxf(m1, bm1);
        const float sf0 = __expf(m0 - nm0);
        const float sf1 = __expf(m1 - nm1);

        float rs0 = 0.0f, rs1 = 0.0f;
#pragma unroll
        for (int nf = 0; nf < 16; nf++) {
            const float p0 = __expf(sacc[nf][0] - nm0);
            const float p1 = __expf(sacc[nf][1] - nm0);
            const float p2 = __expf(sacc[nf][2] - nm1);
            const float p3 = __expf(sacc[nf][3] - nm1);
            sacc[nf][0] = p0; sacc[nf][1] = p1;
            sacc[nf][2] = p2; sacc[nf][3] = p3;
            rs0 += p0 + p1; rs1 += p2 + p3;
        }
        rs0 += __shfl_xor_sync(0xFFFFFFFFu, rs0, 1);
        rs0 += __shfl_xor_sync(0xFFFFFFFFu, rs0, 2);
        rs1 += __shfl_xor_sync(0xFFFFFFFFu, rs1, 1);
        rs1 += __shfl_xor_sync(0xFFFFFFFFu, rs1, 2);

        l0 = l0 * sf0 + rs0;
        l1 = l1 * sf1 + rs1;
        m0 = nm0; m1 = nm1;
#pragma unroll
        for (int nf = 0; nf < 16; nf++) {
            oacc[nf][0] *= sf0; oacc[nf][1] *= sf0;
            oacc[nf][2] *= sf1; oacc[nf][3] *= sf1;
        }

        // ---- O += P @ V
#pragma unroll
        for (int kk = 0; kk < 8; kk++) {
            uint32_t a[4];
            a[0] = packbf(sacc[2 * kk][0],     sacc[2 * kk][1]);
            a[1] = packbf(sacc[2 * kk][2],     sacc[2 * kk][3]);
            a[2] = packbf(sacc[2 * kk + 1][0], sacc[2 * kk + 1][1]);
            a[3] = packbf(sacc[2 * kk + 1][2], sacc[2 * kk + 1][3]);
#pragma unroll
            for (int p = 0; p < 8; p++) {
                uint32_t b[4];
                const int r  = kk * 16 + ((l >> 3) & 1) * 8 + (l & 7);
                const int ck = 2 * p + (l >> 4);
                asm volatile(
                    "ldmatrix.sync.aligned.m8n8.x4.trans.shared.b16 {%0,%1,%2,%3}, [%4];"
                    : "=r"(b[0]), "=r"(b[1]), "=r"(b[2]), "=r"(b[3])
                    : "r"(sw256(sV, r, ck)));
                mma16816(oacc[2 * p],     a, b[0], b[1]);
                mma16816(oacc[2 * p + 1], a, b[2], b[3]);
            }
        }
        __syncthreads();
    }

    // ---- epilogue: O/l + alpha*normed, hi/lo bf16 split
    const float il0 = 1.0f / l0;
    const float il1 = 1.0f / l1;
    const float al  = __ldg(alpha + h);
    const size_t r0g = (size_t)(bq * 128 + w * 16 + (l >> 2));
    const size_t r1g = r0g + 8;

#pragma unroll
    for (int nf = 0; nf < 16; nf++) {
        const size_t cg = (size_t)(col0 + nf * 8 + (l & 3) * 2);
#pragma unroll
        for (int rr = 0; rr < 2; rr++) {
            const size_t row = rr ? r1g : r0g;
            const float il = rr ? il1 : il0;
            const float v0 = oacc[nf][rr * 2 + 0] * il + al * normed[row * D + cg];
            const float v1 = oacc[nf][rr * 2 + 1] * il + al * normed[row * D + cg + 1];
            const __nv_bfloat16 h0 = __float2bfloat16_rn(v0);
            const __nv_bfloat16 h1 = __float2bfloat16_rn(v1);
            const __nv_bfloat16 e0 = __float2bfloat16_rn(v0 - __bfloat162float(h0));
            const __nv_bfloat16 e1 = __float2bfloat16_rn(v1 - __bfloat162float(h1));
            __nv_bfloat162 ph; ph.x = h0; ph.y = h1;
            __nv_bfloat162 pl; pl.x = e0; pl.y = e1;
            *(uint32_t*)(outh + row * D + cg) = *(uint32_t*)&ph;
            *(uint32_t*)(outl + row * D + cg) = *(uint32_t*)&pl;
        }
    }
}

// ---------------------------------------------------------------------------
// Elementwise kernels
// ---------------------------------------------------------------------------
__global__ __launch_bounds__(256) void f32_to_bf16_kernel(
    const float* __restrict__ in, __nv_bfloat16* __restrict__ out, int n4)
{
    const int i = blockIdx.x * 256 + threadIdx.x;
    if (i >= n4) return;
    const float4 v = ((const float4*)in)[i];
    uint2 o;
    o.x = packbf(v.x, v.y);
    o.y = packbf(v.z, v.w);
    ((uint2*)out)[i] = o;
}

__device__ __forceinline__ void split_write4(
    __nv_bfloat16* hi, __nv_bfloat16* lo, size_t idx4,
    float a0, float a1, float a2, float a3)
{
    float a[4] = {a0, a1, a2, a3};
    __nv_bfloat16 h[4], e[4];
#pragma unroll
    for (int j = 0; j < 4; j++) {
        h[j] = __float2bfloat16_rn(a[j]);
        e[j] = __float2bfloat16_rn(a[j] - __bfloat162float(h[j]));
    }
    uint2 ho, lo_;
    ho.x  = packbf(__bfloat162float(h[0]), __bfloat162float(h[1]));
    ho.y  = packbf(__bfloat162float(h[2]), __bfloat162float(h[3]));
    lo_.x = packbf(__bfloat162float(e[0]), __bfloat162float(e[1]));
    lo_.y = packbf(__bfloat162float(e[2]), __bfloat162float(e[3]));
    ((uint2*)hi)[idx4] = ho;
    ((uint2*)lo)[idx4] = lo_;
}

// rmsnorm -> f32 out + hi/lo bf16 split, one block per row
__global__ __launch_bounds__(256) void rmsnorm_split_kernel(
    const float* __restrict__ x, const float* __restrict__ w,
    float* __restrict__ outf, __nv_bfloat16* __restrict__ outh,
    __nv_bfloat16* __restrict__ outl)
{
    __shared__ float red[256];
    const int r = blockIdx.x;
    const int tid = threadIdx.x;
    const float* xr = x + (size_t)r * D;

    float ss = 0.0f;
#pragma unroll
    for (int j4 = tid; j4 < D / 4; j4 += 256) {
        const float4 v = ((const float4*)xr)[j4];
        ss += v.x * v.x + v.y * v.y + v.z * v.z + v.w * v.w;
    }
    red[tid] = ss;
    __syncthreads();
    for (int s = 128; s > 0; s >>= 1) {
        if (tid < s) red[tid] += red[tid + s];
        __syncthreads();
    }
    const float sc = rsqrtf(red[0] / (float)D + 1e-6f);

#pragma unroll
    for (int j4 = tid; j4 < D / 4; j4 += 256) {
        const float4 v  = ((const float4*)xr)[j4];
        const float4 wv = ((const float4*)w)[j4];
        const float o0 = v.x * sc * wv.x;
        const float o1 = v.y * sc * wv.y;
        const float o2 = v.z * sc * wv.z;
        const float o3 = v.w * sc * wv.w;
        float4 of; of.x = o0; of.y = o1; of.z = o2; of.w = o3;
        ((float4*)(outf + (size_t)r * D))[j4] = of;
        split_write4(outh + (size_t)r * D, outl + (size_t)r * D, j4, o0, o1, o2, o3);
    }
}

// h = silu(g)*u -> hi/lo bf16 split
__global__ __launch_bounds__(256) void silu_mul_split_kernel(
    const float* __restrict__ g, const float* __restrict__ u,
    __nv_bfloat16* __restrict__ outh, __nv_bfloat16* __restrict__ outl)
{
    const size_t i = (size_t)blockIdx.x * 256 + threadIdx.x;
    const float4 gv = ((const float4*)g)[i];
    const float4 uv = ((const float4*)u)[i];
    const float a0 = gv.x / (1.0f + __expf(-gv.x)) * uv.x;
    const float a1 = gv.y / (1.0f + __expf(-gv.y)) * uv.y;
    const float a2 = gv.z / (1.0f + __expf(-gv.z)) * uv.z;
    const float a3 = gv.w / (1.0f + __expf(-gv.w)) * uv.w;
    split_write4(outh, outl, i, a0, a1, a2, a3);
}

// ---------------------------------------------------------------------------
// Launch
// ---------------------------------------------------------------------------
extern "C" void kernel_launch(void* const* d_in, const int* in_sizes, int n_in,
                              void* d_out, int out_size)
{
    (void)in_sizes; (void)n_in; (void)out_size;

    const float* x     = (const float*)d_in[0];
    const float* wn_a  = (const float*)d_in[1];
    const float* wn_m  = (const float*)d_in[2];
    const float* Wq    = (const float*)d_in[3];
    const float* sq    = (const float*)d_in[4];
    const float* Wk    = (const float*)d_in[5];
    const float* sk    = (const float*)d_in[6];
    const float* Wv    = (const float*)d_in[7];
    const float* sv    = (const float*)d_in[8];
    const float* Wo    = (const float*)d_in[9];
    const float* so    = (const float*)d_in[10];
    const float* Wg    = (const float*)d_in[11];
    const float* sg    = (const float*)d_in[12];
    const float* Wu    = (const float*)d_in[13];
    const float* su    = (const float*)d_in[14];
    const float* Wd    = (const float*)d_in[15];
    const float* sd    = (const float*)d_in[16];
    const float* alpha = (const float*)d_in[17];
    float* out = (float*)d_out;

    float *normed, *x1, *gate, *up;
    cudaGetSymbolAddress((void**)&normed, g_normed);
    cudaGetSymbolAddress((void**)&x1,     g_x1);
    cudaGetSymbolAddress((void**)&gate,   g_gate);
    cudaGetSymbolAddress((void**)&up,     g_up);

    __nv_bfloat16 *qb, *kb, *vb, *wq, *wk, *wv, *wo, *wg, *wu, *wd, *ah, *al;
    cudaGetSymbolAddress((void**)&qb, g_qb);
    cudaGetSymbolAddress((void**)&kb, g_kb);
    cudaGetSymbolAddress((void**)&vb, g_vb);
    cudaGetSymbolAddress((void**)&wq, g_wq_bf);
    cudaGetSymbolAddress((void**)&wk, g_wk_bf);
    cudaGetSymbolAddress((void**)&wv, g_wv_bf);
    cudaGetSymbolAddress((void**)&wo, g_wo_bf);
    cudaGetSymbolAddress((void**)&wg, g_wg_bf);
    cudaGetSymbolAddress((void**)&wu, g_wu_bf);
    cudaGetSymbolAddress((void**)&wd, g_wd_bf);
    cudaGetSymbolAddress((void**)&ah, g_ah);
    cudaGetSymbolAddress((void**)&al, g_al);

    cudaFuncSetAttribute(mma_gemm, cudaFuncAttributeMaxDynamicSharedMemorySize,
                         MMA_SMEM);
    cudaFuncSetAttribute(flash_attn, cudaFuncAttributeMaxDynamicSharedMemorySize,
                         FL_SMEM);

    const float inv_sqrt_dh = 0.08838834764831845f;  // 1/sqrt(128)

    // 0. weights -> bf16 (exact for ternary)
    const int nDD = D * D / 4, nFD = DFF * D / 4;
    f32_to_bf16_kernel<<<(nDD + 255) / 256, 256>>>(Wq, wq, nDD);
    f32_to_bf16_kernel<<<(nDD + 255) / 256, 256>>>(Wk, wk, nDD);
    f32_to_bf16_kernel<<<(nDD + 255) / 256, 256>>>(Wv, wv, nDD);
    f32_to_bf16_kernel<<<(nDD + 255) / 256, 256>>>(Wo, wo, nDD);
    f32_to_bf16_kernel<<<(nFD + 255) / 256, 256>>>(Wg, wg, nFD);
    f32_to_bf16_kernel<<<(nFD + 255) / 256, 256>>>(Wu, wu, nFD);
    f32_to_bf16_kernel<<<(nFD + 255) / 256, 256>>>(Wd, wd, nFD);

    // 1. rmsnorm (f32 + hi/lo split fused)
    rmsnorm_split_kernel<<<S, 256>>>(x, wn_a, normed, ah, al);

    // 2. q/k/v projections -> bf16 (scales folded; q also gets 1/sqrt(dh))
    mma_gemm<<<dim3(D / 128, S / 128), 256, MMA_SMEM>>>(
        ah, al, wq, nullptr, qb, D, D, sq, inv_sqrt_dh, nullptr);
    mma_gemm<<<dim3(D / 128, S / 128), 256, MMA_SMEM>>>(
        ah, al, wk, nullptr, kb, D, D, sk, 1.0f, nullptr);
    mma_gemm<<<dim3(D / 128, S / 128), 256, MMA_SMEM>>>(
        ah, al, wv, nullptr, vb, D, D, sv, 1.0f, nullptr);

    // 3. flash attention -> hi/lo split of (attn_out + alpha*normed)
    flash_attn<<<dim3(S / 128, H), 256, FL_SMEM>>>(
        qb, kb, vb, normed, alpha, ah, al);

    // 4. x1 = x + attn @ Wo^T * so
    mma_gemm<<<dim3(D / 128, S / 128), 256, MMA_SMEM>>>(
        ah, al, wo, x1, nullptr, D, D, so, 1.0f, x);

    // 5. mlp norm (fused split)
    rmsnorm_split_kernel<<<S, 256>>>(x1, wn_m, normed, ah, al);

    // 6. gate / up
    mma_gemm<<<dim3(DFF / 128, S / 128), 256, MMA_SMEM>>>(
        ah, al, wg, gate, nullptr, D, DFF, sg, 1.0f, nullptr);
    mma_gemm<<<dim3(DFF / 128, S / 128), 256, MMA_SMEM>>>(
        ah, al, wu, up, nullptr, D, DFF, su, 1.0f, nullptr);

    // 7. silu*up -> hi/lo split (fused)
    silu_mul_split_kernel<<<(S * DFF / 4) / 256, 256>>>(gate, up, ah, al);

    // 8. out = x1 + h @ Wd^T * sd
    mma_gemm<<<dim3(D / 128, S / 128), 256, MMA_SMEM>>>(
        ah, al, wd, out, nullptr, DFF, D, sd, 1.0f, x1);
}

// round 7
// speedup vs baseline: 7.2461x; 1.6063x over previous
#include <cuda_runtime.h>
#include <cuda_fp16.h>
#include <cstdint>
#include <math.h>

#define S   2048
#define D   2048
#define DFF 8192
#define H   16
#define DH  128

// ---------------------------------------------------------------------------
// Scratch (device globals; no allocation allowed)
// ---------------------------------------------------------------------------
__device__ float g_normed[(size_t)S * D];
__device__ float g_x1[(size_t)S * D];
__device__ float g_gate[(size_t)S * DFF];
__device__ float g_up[(size_t)S * DFF];

__device__ __half g_qh[(size_t)S * D];
__device__ __half g_kh[(size_t)S * D];
__device__ __half g_vh[(size_t)S * D];

__device__ __half g_wq_h[(size_t)D * D];
__device__ __half g_wk_h[(size_t)D * D];
__device__ __half g_wv_h[(size_t)D * D];
__device__ __half g_wo_h[(size_t)D * D];
__device__ __half g_wg_h[(size_t)DFF * D];
__device__ __half g_wu_h[(size_t)DFF * D];
__device__ __half g_wd_h[(size_t)D * DFF];
__device__ __half g_act[(size_t)S * DFF];      // fp16 activations (max size)

// ---------------------------------------------------------------------------
// helpers
// ---------------------------------------------------------------------------
__device__ __forceinline__ uint32_t smem_u32(const void* p) {
    uint32_t a;
    asm("{ .reg .u64 t; cvta.to.shared.u64 t, %1; cvt.u32.u64 %0, t; }"
        : "=r"(a) : "l"(p));
    return a;
}

__device__ __forceinline__ uint32_t packh(float x, float y) {
    __half2 t = __floats2half2_rn(x, y);
    return *(uint32_t*)&t;
}

__device__ __forceinline__ void mma16816h(float* c, const uint32_t* a,
                                          uint32_t b0, uint32_t b1) {
    asm volatile(
        "mma.sync.aligned.m16n8k16.row.col.f32.f16.f16.f32 "
        "{%0,%1,%2,%3}, {%4,%5,%6,%7}, {%8,%9}, {%0,%1,%2,%3};"
        : "+f"(c[0]), "+f"(c[1]), "+f"(c[2]), "+f"(c[3])
        : "r"(a[0]), "r"(a[1]), "r"(a[2]), "r"(a[3]), "r"(b0), "r"(b1));
}

// ---------------------------------------------------------------------------
// Weight GEMM via mma.sync (fp16 in, fp32 accum).
// C = sc*A@Bw^T (+R), f32 or fp16 output.
// CTA 128x128, BK=32, 8 warps (2x4), warp tile 64x32, 3-stage cp.async.
// Tile rows = 64B; swizzle: ck ^= (row>>1)&3.
// ---------------------------------------------------------------------------
#define TILE_B   8192
#define STAGE_B  (2 * TILE_B)
#define MMA_SMEM (3 * STAGE_B)

__device__ __forceinline__ void cp_tile(
    uint32_t s_tile, const __half* __restrict__ g,
    int row0, int ld, int k0, int tid)
{
#pragma unroll
    for (int i = 0; i < 2; i++) {
        const int idx = tid + i * 256;      // 0..511
        const int r   = idx >> 2;           // row 0..127
        const int ck  = idx & 3;            // 16B chunk 0..3
        const void* src = g + (size_t)(row0 + r) * ld + k0 + ck * 8;
        const uint32_t dst = s_tile + r * 64 + (((ck ^ ((r >> 1) & 3))) << 4);
        asm volatile("cp.async.cg.shared.global [%0], [%1], 16;"
                     :: "r"(dst), "l"(src));
    }
}

__device__ __forceinline__ uint32_t sw_addr(uint32_t s_tile, int row, int ck) {
    return s_tile + row * 64 + ((ck ^ ((row >> 1) & 3)) << 4);
}

__device__ __forceinline__ void load_stage(
    uint32_t stg, const __half* A, const __half* Bw,
    int rowA0, int rowB0, int Ktot, int k0, int tid)
{
    cp_tile(stg,          A,  rowA0, Ktot, k0, tid);
    cp_tile(stg + TILE_B, Bw, rowB0, Ktot, k0, tid);
    asm volatile("cp.async.commit_group;");
}

__global__ __launch_bounds__(256)
void mma_gemm(const __half* __restrict__ A,
              const __half* __restrict__ Bw,
              float* __restrict__ Cf,
              __half* __restrict__ Ch,
              int Ktot, int ldc,
              const float* __restrict__ scale, float scale_const,
              const float* __restrict__ R)
{
    extern __shared__ char smem[];
    const uint32_t sbase = smem_u32(smem);
    const int tid = threadIdx.x;
    const int l   = tid & 31;
    const int w   = tid >> 5;
    const int wm  = w >> 2;
    const int wn  = w & 3;
    const int bm  = blockIdx.y;
    const int bn  = blockIdx.x;
    const int rowA0 = bm * 128;
    const int rowB0 = bn * 128;

    float acc[4][4][4];
#pragma unroll
    for (int i = 0; i < 4; i++)
#pragma unroll
        for (int j = 0; j < 4; j++)
#pragma unroll
            for (int c = 0; c < 4; c++) acc[i][j][c] = 0.0f;

    const int nc = Ktot >> 5;

    load_stage(sbase,           A, Bw, rowA0, rowB0, Ktot, 0,  tid);
    load_stage(sbase + STAGE_B, A, Bw, rowA0, rowB0, Ktot, 32, tid);

    for (int c = 0; c < nc; c++) {
        if (c + 2 < nc) {
            load_stage(sbase + ((c + 2) % 3) * STAGE_B, A, Bw,
                       rowA0, rowB0, Ktot, (c + 2) * 32, tid);
            asm volatile("cp.async.wait_group 2;");
        } else if (c + 1 < nc) {
            asm volatile("cp.async.wait_group 1;");
        } else {
            asm volatile("cp.async.wait_group 0;");
        }
        __syncthreads();

        const uint32_t st = sbase + (c % 3) * STAGE_B;
        const uint32_t sA = st;
        const uint32_t sB = st + TILE_B;

#pragma unroll
        for (int ks = 0; ks < 2; ks++) {
            uint32_t bf[4][2];
#pragma unroll
            for (int nf = 0; nf < 4; nf++) {
                const int nrow = wn * 32 + nf * 8 + (l & 7);
                const int ck   = ks * 2 + ((l >> 3) & 1);
                asm volatile(
                    "ldmatrix.sync.aligned.m8n8.x2.shared.b16 {%0,%1}, [%2];"
                    : "=r"(bf[nf][0]), "=r"(bf[nf][1])
                    : "r"(sw_addr(sB, nrow, ck)));
            }
            uint32_t af[4][4];
#pragma unroll
            for (int mf = 0; mf < 4; mf++) {
                const int arow = wm * 64 + mf * 16 + (l & 15);
                const int ck   = ks * 2 + (l >> 4);
                asm volatile(
                    "ldmatrix.sync.aligned.m8n8.x4.shared.b16 {%0,%1,%2,%3}, [%4];"
                    : "=r"(af[mf][0]), "=r"(af[mf][1]),
                      "=r"(af[mf][2]), "=r"(af[mf][3])
                    : "r"(sw_addr(sA, arow, ck)));
            }
#pragma unroll
            for (int mf = 0; mf < 4; mf++)
#pragma unroll
                for (int nf = 0; nf < 4; nf++)
                    mma16816h(acc[mf][nf], af[mf], bf[nf][0], bf[nf][1]);
        }
        __syncthreads();
    }

    float sc = scale_const;
    if (scale) sc *= __ldg(scale);
    const int qrow = l >> 2;
    const int qcol = (l & 3) * 2;

#pragma unroll
    for (int mf = 0; mf < 4; mf++) {
        const size_t r0 = (size_t)(bm * 128 + wm * 64 + mf * 16 + qrow);
#pragma unroll
        for (int nf = 0; nf < 4; nf++) {
            const size_t c0 = (size_t)(bn * 128 + wn * 32 + nf * 8 + qcol);
#pragma unroll
            for (int half = 0; half < 2; half++) {
                const size_t row = r0 + half * 8;
                const size_t off = row * ldc + c0;
                float ox = acc[mf][nf][half * 2 + 0] * sc;
                float oy = acc[mf][nf][half * 2 + 1] * sc;
                if (Ch) {
                    *(uint32_t*)(Ch + off) = packh(ox, oy);
                } else {
                    if (R) {
                        const float2 rv = *(const float2*)(R + off);
                        ox += rv.x; oy += rv.y;
                    }
                    float2 o; o.x = ox; o.y = oy;
                    *(float2*)(Cf + off) = o;
                }
            }
        }
    }
}

// ---------------------------------------------------------------------------
// Flash attention (fp16 tensor cores, fp32 online softmax).
// grid = (S/128, H), block = 256 (8 warps, 16 rows each).
// Tiles: 128 rows x 256B; swizzle ck' = ((ck&7)^(row&7)) | (ck&8).
// Epilogue: out = O/l + alpha[h]*normed, written fp16.
// ---------------------------------------------------------------------------
#define FL_STAGE 65536
#define FL_SMEM  (2 * FL_STAGE)

__device__ __forceinline__ uint32_t sw256(uint32_t base, int row, int ck) {
    return base + row * 256 + (((((ck & 7) ^ (row & 7))) | (ck & 8)) << 4);
}

__device__ __forceinline__ void cp_tile256(
    uint32_t s_tile, const __half* __restrict__ g,
    int row0, int col0, int tid)
{
#pragma unroll
    for (int i = 0; i < 8; i++) {
        const int idx = tid + i * 256;
        const int r  = idx >> 4;
        const int ck = idx & 15;
        const void* src = g + (size_t)(row0 + r) * D + col0 + ck * 8;
        asm volatile("cp.async.cg.shared.global [%0], [%1], 16;"
                     :: "r"(sw256(s_tile, r, ck)), "l"(src));
    }
}

__global__ __launch_bounds__(256)
void flash_attn(const __half* __restrict__ Qh,
                const __half* __restrict__ Kh,
                const __half* __restrict__ Vh,
                const float* __restrict__ normed,
                const float* __restrict__ alpha,
                __half* __restrict__ outh)
{
    extern __shared__ char smem[];
    const uint32_t sbase = smem_u32(smem);
    const int tid = threadIdx.x;
    const int l   = tid & 31;
    const int w   = tid >> 5;
    const int bq  = blockIdx.x;
    const int h   = blockIdx.y;
    const int col0 = h * DH;

    // Q tile -> stage0 smem -> registers
    cp_tile256(sbase, Qh, bq * 128, col0, tid);
    asm volatile("cp.async.commit_group;");
    asm volatile("cp.async.wait_group 0;");
    __syncthreads();

    uint32_t qf[8][4];
#pragma unroll
    for (int kk = 0; kk < 8; kk++) {
        const int r  = w * 16 + (l & 15);
        const int ck = kk * 2 + (l >> 4);
        asm volatile("ldmatrix.sync.aligned.m8n8.x4.shared.b16 {%0,%1,%2,%3}, [%4];"
            : "=r"(qf[kk][0]), "=r"(qf[kk][1]), "=r"(qf[kk][2]), "=r"(qf[kk][3])
            : "r"(sw256(sbase, r, ck)));
    }
    __syncthreads();

    float oacc[16][4];
#pragma unroll
    for (int i = 0; i < 16; i++)
#pragma unroll
        for (int j = 0; j < 4; j++) oacc[i][j] = 0.0f;
    float m0 = -1e30f, m1 = -1e30f, l0 = 0.0f, l1 = 0.0f;

    cp_tile256(sbase,         Kh, 0, col0, tid);
    cp_tile256(sbase + 32768, Vh, 0, col0, tid);
    asm volatile("cp.async.commit_group;");

    for (int kb = 0; kb <= bq; kb++) {
        if (kb + 1 <= bq) {
            const uint32_t nb = sbase + ((kb + 1) & 1) * FL_STAGE;
            cp_tile256(nb,         Kh, (kb + 1) * 128, col0, tid);
            cp_tile256(nb + 32768, Vh, (kb + 1) * 128, col0, tid);
            asm volatile("cp.async.commit_group;");
            asm volatile("cp.async.wait_group 1;");
        } else {
            asm volatile("cp.async.wait_group 0;");
        }
        __syncthreads();

        const uint32_t sK = sbase + (kb & 1) * FL_STAGE;
        const uint32_t sV = sK + 32768;

        // ---- S = Q @ K^T
        float sacc[16][4];
#pragma unroll
        for (int i = 0; i < 16; i++)
#pragma unroll
            for (int j = 0; j < 4; j++) sacc[i][j] = 0.0f;

#pragma unroll
        for (int kk = 0; kk < 8; kk++) {
#pragma unroll
            for (int p = 0; p < 8; p++) {
                uint32_t b[4];
                const int r  = p * 16 + ((l >> 4) << 3) + (l & 7);
                const int ck = kk * 2 + ((l >> 3) & 1);
                asm volatile(
                    "ldmatrix.sync.aligned.m8n8.x4.shared.b16 {%0,%1,%2,%3}, [%4];"
                    : "=r"(b[0]), "=r"(b[1]), "=r"(b[2]), "=r"(b[3])
                    : "r"(sw256(sK, r, ck)));
                mma16816h(sacc[2 * p],     qf[kk], b[0], b[1]);
                mma16816h(sacc[2 * p + 1], qf[kk], b[2], b[3]);
            }
        }

        // ---- causal mask on diagonal block
        if (kb == bq) {
            const int r0 = w * 16 + (l >> 2);
#pragma unroll
            for (int nf = 0; nf < 16; nf++) {
                const int c0 = nf * 8 + (l & 3) * 2;
                if (c0     > r0)     sacc[nf][0] = -1e30f;
                if (c0 + 1 > r0)     sacc[nf][1] = -1e30f;
                if (c0     > r0 + 8) sacc[nf][2] = -1e30f;
                if (c0 + 1 > r0 + 8) sacc[nf][3] = -1e30f;
            }
        }

        // ---- online softmax
        float bm0 = -1e30f, bm1 = -1e30f;
#pragma unroll
        for (int nf = 0; nf < 16; nf++) {
            bm0 = fmaxf(bm0, fmaxf(sacc[nf][0], sacc[nf][1]));
            bm1 = fmaxf(bm1, fmaxf(sacc[nf][2], sacc[nf][3]));
        }
        bm0 = fmaxf(bm0, __shfl_xor_sync(0xFFFFFFFFu, bm0, 1));
        bm0 = fmaxf(bm0, __shfl_xor_sync(0xFFFFFFFFu, bm0, 2));
        bm1 = fmaxf(bm1, __shfl_xor_sync(0xFFFFFFFFu, bm1, 1));
        bm1 = fmaxf(bm1, __shfl_xor_sync(0xFFFFFFFFu, bm1, 2));

        const float nm0 = fmaxf(m0, bm0);
        const float nm1 = fmaxf(m1, bm1);
        const float sf0 = __expf(m0 - nm0);
        const float sf1 = __expf(m1 - nm1);

        float rs0 = 0.0f, rs1 = 0.0f;
#pragma unroll
        for (int nf = 0; nf < 16; nf++) {
            const float p0 = __expf(sacc[nf][0] - nm0);
            const float p1 = __expf(sacc[nf][1] - nm0);
            const float p2 = __expf(sacc[nf][2] - nm1);
            const float p3 = __expf(sacc[nf][3] - nm1);
            sacc[nf][0] = p0; sacc[nf][1] = p1;
            sacc[nf][2] = p2; sacc[nf][3] = p3;
            rs0 += p0 + p1; rs1 += p2 + p3;
        }
        rs0 += __shfl_xor_sync(0xFFFFFFFFu, rs0, 1);
        rs0 += __shfl_xor_sync(0xFFFFFFFFu, rs0, 2);
        rs1 += __shfl_xor_sync(0xFFFFFFFFu, rs1, 1);
        rs1 += __shfl_xor_sync(0xFFFFFFFFu, rs1, 2);

        l0 = l0 * sf0 + rs0;
        l1 = l1 * sf1 + rs1;
        m0 = nm0; m1 = nm1;
#pragma unroll
        for (int nf = 0; nf < 16; nf++) {
            oacc[nf][0] *= sf0; oacc[nf][1] *= sf0;
            oacc[nf][2] *= sf1; oacc[nf][3] *= sf1;
        }

        // ---- O += P @ V
#pragma unroll
        for (int kk = 0; kk < 8; kk++) {
            uint32_t a[4];
            a[0] = packh(sacc[2 * kk][0],     sacc[2 * kk][1]);
            a[1] = packh(sacc[2 * kk][2],     sacc[2 * kk][3]);
            a[2] = packh(sacc[2 * kk + 1][0], sacc[2 * kk + 1][1]);
            a[3] = packh(sacc[2 * kk + 1][2], sacc[2 * kk + 1][3]);
#pragma unroll
            for (int p = 0; p < 8; p++) {
                uint32_t b[4];
                const int r  = kk * 16 + ((l >> 3) & 1) * 8 + (l & 7);
                const int ck = 2 * p + (l >> 4);
                asm volatile(
                    "ldmatrix.sync.aligned.m8n8.x4.trans.shared.b16 {%0,%1,%2,%3}, [%4];"
                    : "=r"(b[0]), "=r"(b[1]), "=r"(b[2]), "=r"(b[3])
                    : "r"(sw256(sV, r, ck)));
                mma16816h(oacc[2 * p],     a, b[0], b[1]);
                mma16816h(oacc[2 * p + 1], a, b[2], b[3]);
            }
        }
        __syncthreads();
    }

    // ---- epilogue: O/l + alpha*normed -> fp16
    const float il0 = 1.0f / l0;
    const float il1 = 1.0f / l1;
    const float al  = __ldg(alpha + h);
    const size_t r0g = (size_t)(bq * 128 + w * 16 + (l >> 2));
    const size_t r1g = r0g + 8;

#pragma unroll
    for (int nf = 0; nf < 16; nf++) {
        const size_t cg = (size_t)(col0 + nf * 8 + (l & 3) * 2);
#pragma unroll
        for (int rr = 0; rr < 2; rr++) {
            const size_t row = rr ? r1g : r0g;
            const float il = rr ? il1 : il0;
            const float v0 = oacc[nf][rr * 2 + 0] * il + al * normed[row * D + cg];
            const float v1 = oacc[nf][rr * 2 + 1] * il + al * normed[row * D + cg + 1];
            *(uint32_t*)(outh + row * D + cg) = packh(v0, v1);
        }
    }
}

// ---------------------------------------------------------------------------
// Elementwise kernels
// ---------------------------------------------------------------------------
__global__ __launch_bounds__(256) void f32_to_fp16_kernel(
    const float* __restrict__ in, __half* __restrict__ out, int n4)
{
    const int i = blockIdx.x * 256 + threadIdx.x;
    if (i >= n4) return;
    const float4 v = ((const float4*)in)[i];
    uint2 o;
    o.x = packh(v.x, v.y);
    o.y = packh(v.z, v.w);
    ((uint2*)out)[i] = o;
}

// rmsnorm -> f32 out + fp16 out, one block per row
__global__ __launch_bounds__(256) void rmsnorm_h_kernel(
    const float* __restrict__ x, const float* __restrict__ w,
    float* __restrict__ outf, __half* __restrict__ outh)
{
    __shared__ float red[256];
    const int r = blockIdx.x;
    const int tid = threadIdx.x;
    const float* xr = x + (size_t)r * D;

    float ss = 0.0f;
#pragma unroll
    for (int j4 = tid; j4 < D / 4; j4 += 256) {
        const float4 v = ((const float4*)xr)[j4];
        ss += v.x * v.x + v.y * v.y + v.z * v.z + v.w * v.w;
    }
    red[tid] = ss;
    __syncthreads();
    for (int s = 128; s > 0; s >>= 1) {
        if (tid < s) red[tid] += red[tid + s];
        __syncthreads();
    }
    const float sc = rsqrtf(red[0] / (float)D + 1e-6f);

#pragma unroll
    for (int j4 = tid; j4 < D / 4; j4 += 256) {
        const float4 v  = ((const float4*)xr)[j4];
        const float4 wv = ((const float4*)w)[j4];
        const float o0 = v.x * sc * wv.x;
        const float o1 = v.y * sc * wv.y;
        const float o2 = v.z * sc * wv.z;
        const float o3 = v.w * sc * wv.w;
        float4 of; of.x = o0; of.y = o1; of.z = o2; of.w = o3;
        ((float4*)(outf + (size_t)r * D))[j4] = of;
        uint2 oh;
        oh.x = packh(o0, o1);
        oh.y = packh(o2, o3);
        ((uint2*)(outh + (size_t)r * D))[j4] = oh;
    }
}

// h = silu(g)*u -> fp16
__global__ __launch_bounds__(256) void silu_mul_h_kernel(
    const float* __restrict__ g, const float* __restrict__ u,
    __half* __restrict__ outh)
{
    const size_t i = (size_t)blockIdx.x * 256 + threadIdx.x;
    const float4 gv = ((const float4*)g)[i];
    const float4 uv = ((const float4*)u)[i];
    const float a0 = gv.x / (1.0f + __expf(-gv.x)) * uv.x;
    const float a1 = gv.y / (1.0f + __expf(-gv.y)) * uv.y;
    const float a2 = gv.z / (1.0f + __expf(-gv.z)) * uv.z;
    const float a3 = gv.w / (1.0f + __expf(-gv.w)) * uv.w;
    uint2 o;
    o.x = packh(a0, a1);
    o.y = packh(a2, a3);
    ((uint2*)outh)[i] = o;
}

// ---------------------------------------------------------------------------
// Launch
// ---------------------------------------------------------------------------
extern "C" void kernel_launch(void* const* d_in, const int* in_sizes, int n_in,
                              void* d_out, int out_size)
{
    (void)in_sizes; (void)n_in; (void)out_size;

    const float* x     = (const float*)d_in[0];
    const float* wn_a  = (const float*)d_in[1];
    const float* wn_m  = (const float*)d_in[2];
    const float* Wq    = (const float*)d_in[3];
    const float* sq    = (const float*)d_in[4];
    const float* Wk    = (const float*)d_in[5];
    const float* sk    = (const float*)d_in[6];
    const float* Wv    = (const float*)d_in[7];
    const float* sv    = (const float*)d_in[8];
    const float* Wo    = (const float*)d_in[9];
    const float* so    = (const float*)d_in[10];
    const float* Wg    = (const float*)d_in[11];
    const float* sg    = (const float*)d_in[12];
    const float* Wu    = (const float*)d_in[13];
    const float* su    = (const float*)d_in[14];
    const float* Wd    = (const float*)d_in[15];
    const float* sd    = (const float*)d_in[16];
    const float* alpha = (const float*)d_in[17];
    float* out = (float*)d_out;

    float *normed, *x1, *gate, *up;
    cudaGetSymbolAddress((void**)&normed, g_normed);
    cudaGetSymbolAddress((void**)&x1,     g_x1);
    cudaGetSymbolAddress((void**)&gate,   g_gate);
    cudaGetSymbolAddress((void**)&up,     g_up);

    __half *qh, *kh, *vh, *wq, *wk, *wv, *wo, *wg, *wu, *wd, *act;
    cudaGetSymbolAddress((void**)&qh, g_qh);
    cudaGetSymbolAddress((void**)&kh, g_kh);
    cudaGetSymbolAddress((void**)&vh, g_vh);
    cudaGetSymbolAddress((void**)&wq, g_wq_h);
    cudaGetSymbolAddress((void**)&wk, g_wk_h);
    cudaGetSymbolAddress((void**)&wv, g_wv_h);
    cudaGetSymbolAddress((void**)&wo, g_wo_h);
    cudaGetSymbolAddress((void**)&wg, g_wg_h);
    cudaGetSymbolAddress((void**)&wu, g_wu_h);
    cudaGetSymbolAddress((void**)&wd, g_wd_h);
    cudaGetSymbolAddress((void**)&act, g_act);

    cudaFuncSetAttribute(mma_gemm, cudaFuncAttributeMaxDynamicSharedMemorySize,
                         MMA_SMEM);
    cudaFuncSetAttribute(flash_attn, cudaFuncAttributeMaxDynamicSharedMemorySize,
                         FL_SMEM);

    const float inv_sqrt_dh = 0.08838834764831845f;  // 1/sqrt(128)

    // 0. weights -> fp16 (exact for ternary)
    const int nDD = D * D / 4, nFD = DFF * D / 4;
    f32_to_fp16_kernel<<<(nDD + 255) / 256, 256>>>(Wq, wq, nDD);
    f32_to_fp16_kernel<<<(nDD + 255) / 256, 256>>>(Wk, wk, nDD);
    f32_to_fp16_kernel<<<(nDD + 255) / 256, 256>>>(Wv, wv, nDD);
    f32_to_fp16_kernel<<<(nDD + 255) / 256, 256>>>(Wo, wo, nDD);
    f32_to_fp16_kernel<<<(nFD + 255) / 256, 256>>>(Wg, wg, nFD);
    f32_to_fp16_kernel<<<(nFD + 255) / 256, 256>>>(Wu, wu, nFD);
    f32_to_fp16_kernel<<<(nFD + 255) / 256, 256>>>(Wd, wd, nFD);

    // 1. rmsnorm (f32 + fp16 fused)
    rmsnorm_h_kernel<<<S, 256>>>(x, wn_a, normed, act);

    // 2. q/k/v projections -> fp16 (scales folded; q also gets 1/sqrt(dh))
    mma_gemm<<<dim3(D / 128, S / 128), 256, MMA_SMEM>>>(
        act, wq, nullptr, qh, D, D, sq, inv_sqrt_dh, nullptr);
    mma_gemm<<<dim3(D / 128, S / 128), 256, MMA_SMEM>>>(
        act, wk, nullptr, kh, D, D, sk, 1.0f, nullptr);
    mma_gemm<<<dim3(D / 128, S / 128), 256, MMA_SMEM>>>(
        act, wv, nullptr, vh, D, D, sv, 1.0f, nullptr);

    // 3. flash attention -> fp16 (attn_out + alpha*normed)
    flash_attn<<<dim3(S / 128, H), 256, FL_SMEM>>>(
        qh, kh, vh, normed, alpha, act);

    // 4. x1 = x + attn @ Wo^T * so
    mma_gemm<<<dim3(D / 128, S / 128), 256, MMA_SMEM>>>(
        act, wo, x1, nullptr, D, D, so, 1.0f, x);

    // 5. mlp norm (fused fp16)
    rmsnorm_h_kernel<<<S, 256>>>(x1, wn_m, normed, act);

    // 6. gate / up
    mma_gemm<<<dim3(DFF / 128, S / 128), 256, MMA_SMEM>>>(
        act, wg, gate, nullptr, D, DFF, sg, 1.0f, nullptr);
    mma_gemm<<<dim3(DFF / 128, S / 128), 256, MMA_SMEM>>>(
        act, wu, up, nullptr, D, DFF, su, 1.0f, nullptr);

    // 7. silu*up -> fp16
    silu_mul_h_kernel<<<(S * DFF / 4) / 256, 256>>>(gate, up, act);

    // 8. out = x1 + h @ Wd^T * sd
    mma_gemm<<<dim3(D / 128, S / 128), 256, MMA_SMEM>>>(
        act, wd, out, nullptr, DFF, D, sd, 1.0f, x1);
}